// round 1
// baseline (speedup 1.0000x reference)
#include <cuda_runtime.h>
#include <math.h>

// ---------------------------------------------------------------------------
// AFT attention:  B=8, T=2048, D=1024, M=B*T=16384
//   proj = x @ w_attn                [16384, 3072]   (q|k|v)
//   ke   = exp(k - rowmax(k));  kv = ke * v    (in place over k,v slots)
//   eb[i,j] = exp(pb[i,j] - rowmax_{j<=i}(pb)) for j<=i else 0
//   nd[b]  = eb @ [ke | kv][b]      ->  cols 0..1023 = denom, 1024..2047 = num
//   y      = sigmoid(q) * num / denom
//   out    = y @ w_proj
// ---------------------------------------------------------------------------

#define BM 128
#define BN 128
#define BK 8
#define TM 8
#define TN 8

// scratch (static device memory; allocation-guard safe)
__device__ float g_proj[16384u * 3072u];     // 192 MB
__device__ float g_expbias[2048u * 2048u];   //  16 MB
__device__ float g_nd[8u * 2048u * 2048u];   // 128 MB
__device__ float g_y[16384u * 1024u];        //  64 MB

// ---------------------------------------------------------------------------
// Generic fp32 GEMM:  C[bz] = A @ B[bz],   A row-major [M,K] (lda),
// B row-major [K,N] (ldb), C row-major [M,N] (ldc).
// causal != 0: K-loop clamped to (blockRow+1)*BM (A lower-triangular).
// ---------------------------------------------------------------------------
__global__ __launch_bounds__(256) void gemm_f32(
    const float* __restrict__ A, const float* __restrict__ B,
    float* __restrict__ C, int K, int lda, int ldb, int ldc,
    long long strideB, long long strideC, int causal)
{
    __shared__ float As[2][BK][BM];
    __shared__ float Bs[2][BK][BN];

    const int bz = blockIdx.z;
    B += (long long)bz * strideB;
    C += (long long)bz * strideC;

    const int bm = blockIdx.y, bn = blockIdx.x;
    const int tid = threadIdx.x;

    int Klen = K;
    if (causal) { int km = (bm + 1) * BM; if (km < Klen) Klen = km; }
    const int KT = Klen / BK;

    // A tile load: 128 rows x 8 cols, one float4 per thread
    const int arow = tid >> 1;
    const int acol = (tid & 1) * 4;
    const float* Aptr = A + (long long)(bm * BM + arow) * lda + acol;

    // B tile load: 8 rows x 128 cols, one float4 per thread
    const int brow = tid >> 5;
    const int bcol = (tid & 31) * 4;
    const float* Bptr = B + (long long)brow * ldb + bn * BN + bcol;

    const int ty = tid >> 4, tx = tid & 15;
    const int row0 = ty * TM, col0 = tx * TN;

    float acc[TM][TN];
    #pragma unroll
    for (int i = 0; i < TM; i++)
        #pragma unroll
        for (int j = 0; j < TN; j++) acc[i][j] = 0.f;

    // prologue: tile 0 -> buffer 0
    float4 aReg = *(const float4*)Aptr;
    float4 bReg = *(const float4*)Bptr;
    As[0][acol + 0][arow] = aReg.x;
    As[0][acol + 1][arow] = aReg.y;
    As[0][acol + 2][arow] = aReg.z;
    As[0][acol + 3][arow] = aReg.w;
    *(float4*)&Bs[0][brow][bcol] = bReg;
    __syncthreads();

    for (int kt = 0; kt < KT; kt++) {
        const int cur = kt & 1;
        if (kt + 1 < KT) {
            aReg = *(const float4*)(Aptr + (kt + 1) * BK);
            bReg = *(const float4*)(Bptr + (long long)(kt + 1) * BK * ldb);
        }
        #pragma unroll
        for (int kk = 0; kk < BK; kk++) {
            float a[TM], b[TN];
            *(float4*)&a[0] = *(const float4*)&As[cur][kk][row0];
            *(float4*)&a[4] = *(const float4*)&As[cur][kk][row0 + 4];
            *(float4*)&b[0] = *(const float4*)&Bs[cur][kk][col0];
            *(float4*)&b[4] = *(const float4*)&Bs[cur][kk][col0 + 4];
            #pragma unroll
            for (int i = 0; i < TM; i++)
                #pragma unroll
                for (int j = 0; j < TN; j++)
                    acc[i][j] = fmaf(a[i], b[j], acc[i][j]);
        }
        if (kt + 1 < KT) {
            const int nxt = cur ^ 1;
            As[nxt][acol + 0][arow] = aReg.x;
            As[nxt][acol + 1][arow] = aReg.y;
            As[nxt][acol + 2][arow] = aReg.z;
            As[nxt][acol + 3][arow] = aReg.w;
            *(float4*)&Bs[nxt][brow][bcol] = bReg;
            __syncthreads();
        }
    }

    #pragma unroll
    for (int i = 0; i < TM; i++) {
        float* Crow = C + (long long)(bm * BM + row0 + i) * ldc + bn * BN + col0;
        *(float4*)&Crow[0] = make_float4(acc[i][0], acc[i][1], acc[i][2], acc[i][3]);
        *(float4*)&Crow[4] = make_float4(acc[i][4], acc[i][5], acc[i][6], acc[i][7]);
    }
}

// ---------------------------------------------------------------------------
// Per (b,t) row: ke = exp(k - max(k)); kv = ke*v. In place over k,v slots.
// ---------------------------------------------------------------------------
__global__ __launch_bounds__(256) void kv_transform(float* __restrict__ proj)
{
    const long long row = blockIdx.x;
    float* kp = proj + row * 3072 + 1024;
    float* vp = proj + row * 3072 + 2048;
    __shared__ float red[256];
    const int tid = threadIdx.x;

    float m = -INFINITY;
    #pragma unroll
    for (int i = 0; i < 4; i++) m = fmaxf(m, kp[tid + 256 * i]);
    red[tid] = m;
    __syncthreads();
    #pragma unroll
    for (int s = 128; s > 0; s >>= 1) {
        if (tid < s) red[tid] = fmaxf(red[tid], red[tid + s]);
        __syncthreads();
    }
    const float mk = red[0];

    #pragma unroll
    for (int i = 0; i < 4; i++) {
        const int idx = tid + 256 * i;
        const float ke = expf(kp[idx] - mk);
        const float kv = ke * vp[idx];
        kp[idx] = ke;
        vp[idx] = kv;
    }
}

// ---------------------------------------------------------------------------
// expbias row i: max over j<=i, then exp(pb-max) for j<=i else 0.
// ---------------------------------------------------------------------------
__global__ __launch_bounds__(256) void build_expbias(
    const float* __restrict__ pb, float* __restrict__ eb)
{
    const int i = blockIdx.x;
    const float* row = pb + (long long)i * 2048;
    float* out = eb + (long long)i * 2048;
    __shared__ float red[256];
    const int tid = threadIdx.x;

    float m = -INFINITY;
    for (int j = tid; j <= i; j += 256) m = fmaxf(m, row[j]);
    red[tid] = m;
    __syncthreads();
    #pragma unroll
    for (int s = 128; s > 0; s >>= 1) {
        if (tid < s) red[tid] = fmaxf(red[tid], red[tid + s]);
        __syncthreads();
    }
    const float mb = red[0];

    for (int j = tid; j < 2048; j += 256)
        out[j] = (j <= i) ? expf(row[j] - mb) : 0.f;
}

// ---------------------------------------------------------------------------
// y = sigmoid(q) * num / denom     (float4 per thread)
// nd layout per row: [0..1023] = denom (ke), [1024..2047] = num (kv)
// ---------------------------------------------------------------------------
__global__ __launch_bounds__(256) void combine(
    const float* __restrict__ proj, const float* __restrict__ nd,
    float* __restrict__ y)
{
    const long long idx = (long long)blockIdx.x * blockDim.x + threadIdx.x; // float4 idx
    const long long m = idx >> 8;          // 1024/4 = 256 float4 per row
    const int d4 = (int)(idx & 255) * 4;

    const float4 q4  = *(const float4*)(proj + m * 3072 + d4);
    const float4 den = *(const float4*)(nd + m * 2048 + d4);
    const float4 num = *(const float4*)(nd + m * 2048 + 1024 + d4);

    float4 r;
    r.x = (num.x / den.x) / (1.f + expf(-q4.x));
    r.y = (num.y / den.y) / (1.f + expf(-q4.y));
    r.z = (num.z / den.z) / (1.f + expf(-q4.z));
    r.w = (num.w / den.w) / (1.f + expf(-q4.w));
    *(float4*)(y + m * 1024 + d4) = r;
}

// ---------------------------------------------------------------------------
extern "C" void kernel_launch(void* const* d_in, const int* in_sizes, int n_in,
                              void* d_out, int out_size)
{
    const float* x      = (const float*)d_in[0];   // [8,2048,1024]
    const float* w_attn = (const float*)d_in[1];   // [1024,3072]
    const float* w_proj = (const float*)d_in[2];   // [1024,1024]
    const float* pb     = (const float*)d_in[3];   // [2048,2048]
    float* out = (float*)d_out;                    // [8,2048,1024]

    float *proj, *eb, *nd, *y;
    cudaGetSymbolAddress((void**)&proj, g_proj);
    cudaGetSymbolAddress((void**)&eb,   g_expbias);
    cudaGetSymbolAddress((void**)&nd,   g_nd);
    cudaGetSymbolAddress((void**)&y,    g_y);

    // K1: proj = x @ w_attn        [16384,1024] x [1024,3072]
    gemm_f32<<<dim3(3072 / BN, 16384 / BM, 1), 256>>>(
        x, w_attn, proj, 1024, 1024, 3072, 3072, 0, 0, 0);

    // K2a: ke/kv in place
    kv_transform<<<16384, 256>>>(proj);

    // K2b: expbias
    build_expbias<<<2048, 256>>>(pb, eb);

    // K3: nd[b] = eb @ [ke|kv][b]  [2048,2048] x [2048,2048] per batch (causal)
    gemm_f32<<<dim3(2048 / BN, 2048 / BM, 8), 256>>>(
        eb, proj + 1024, nd, 2048, 2048, 3072, 2048,
        (long long)2048 * 3072, (long long)2048 * 2048, 1);

    // K4: y = sigmoid(q) * num / denom
    combine<<<16384, 256>>>(proj, nd, y);

    // K5: out = y @ w_proj         [16384,1024] x [1024,1024]
    gemm_f32<<<dim3(1024 / BN, 16384 / BM, 1), 256>>>(
        y, w_proj, out, 1024, 1024, 1024, 1024, 0, 0, 0);
}

// round 5
// speedup vs baseline: 2.4291x; 2.4291x over previous
#include <cuda_runtime.h>
#include <cuda_bf16.h>
#include <cstdint>
#include <math.h>

// ===========================================================================
// AFT attention via mma.sync bf16 (fp32-accurate 3-term hi/lo split).
// The 3 terms (Ah*Bh + Ah*Bl + Al*Bh) are packed into K: every original
// 32-wide k-chunk expands to 96 = [Ah|Ah|Al] x [Bh|Bl|Bh], so each GEMM is a
// single plain bf16 TN GEMM over K' = 3K. A [M,K'] K-major, B [N,K'] K-major.
// y3 aliases x3 (x3 dead after K1) to shrink static scratch.
// ===========================================================================

#define BM 128
#define BN 128
#define BK 32
#define STG 4
#define TILE_BYTES 8192          // 128 rows x 32 bf16
#define STAGE_BYTES 16384        // A tile + B tile
#define GEMM_SMEM (STG * STAGE_BYTES)

// ---------------- scratch ---------------------------------------------------
__device__ float         g_proj[16384ull * 3072];        // q | k | v fp32
__device__ float         g_nd[8ull * 2048 * 2048];       // denom | num fp32
__device__ __nv_bfloat16 g_x3[16384ull * 3072];          // x triplet, reused as y3
__device__ __nv_bfloat16 g_wa3[3072ull * 3072];          // w_attn^T triplet
__device__ __nv_bfloat16 g_wp3[1024ull * 3072];          // w_proj^T triplet
__device__ __nv_bfloat16 g_eb3[2048ull * 6144];          // expbias triplet (K'=6144)
__device__ __nv_bfloat16 g_kv3[8ull * 2048 * 6144];      // [ke|kv]^T triplet

// ---------------- helpers ---------------------------------------------------
__device__ __forceinline__ uint32_t smem_u32(const void* p) {
    uint32_t a;
    asm("{ .reg .u64 t; cvta.to.shared.u64 t, %1; cvt.u32.u64 %0, t; }"
        : "=r"(a) : "l"(p));
    return a;
}
__device__ __forceinline__ void cp16(uint32_t s, const void* g) {
    asm volatile("cp.async.cg.shared.global [%0], [%1], 16;" :: "r"(s), "l"(g));
}
#define CP_COMMIT() asm volatile("cp.async.commit_group;" ::: "memory")
#define CP_WAIT2()  asm volatile("cp.async.wait_group 2;" ::: "memory")

__device__ __forceinline__ void ldsm4(uint32_t* r, uint32_t addr) {
    asm volatile("ldmatrix.sync.aligned.m8n8.x4.shared.b16 {%0,%1,%2,%3}, [%4];"
        : "=r"(r[0]), "=r"(r[1]), "=r"(r[2]), "=r"(r[3]) : "r"(addr));
}
__device__ __forceinline__ void mma16816(float* d, const uint32_t* a,
                                         uint32_t b0, uint32_t b1) {
    asm volatile(
        "mma.sync.aligned.m16n8k16.row.col.f32.bf16.bf16.f32 "
        "{%0,%1,%2,%3}, {%4,%5,%6,%7}, {%8,%9}, {%0,%1,%2,%3};"
        : "+f"(d[0]), "+f"(d[1]), "+f"(d[2]), "+f"(d[3])
        : "r"(a[0]), "r"(a[1]), "r"(a[2]), "r"(a[3]), "r"(b0), "r"(b1));
}

// 16B-granule swizzle: tile row (0..127) has 4 granules; granule col c
// remapped so any 8 consecutive rows at fixed c hit 8 distinct 16B banks.
__device__ __forceinline__ uint32_t swz16(int row, int c) {
    return (uint32_t)((row << 2) + (c ^ ((row >> 1) & 3))) << 4;
}

// ---------------- GEMM (bf16 TN, cp.async 4-stage, mma.sync) ----------------
__device__ __forceinline__ void issue_stage(uint32_t sbase,
    const __nv_bfloat16* __restrict__ Ag, const __nv_bfloat16* __restrict__ Bg,
    int K3, int kt, int tid)
{
    const uint32_t sa = sbase + (uint32_t)(kt & 3) * STAGE_BYTES;
    const int row = tid >> 2, c = tid & 3;
    const size_t rstride = (size_t)K3 * 2;               // bytes per row
    const size_t goff = (size_t)row * rstride + (size_t)kt * 64 + c * 16;
    cp16(sa + swz16(row, c),                   (const char*)Ag + goff);
    cp16(sa + swz16(row + 64, c),              (const char*)Ag + goff + 64 * rstride);
    cp16(sa + TILE_BYTES + swz16(row, c),      (const char*)Bg + goff);
    cp16(sa + TILE_BYTES + swz16(row + 64, c), (const char*)Bg + goff + 64 * rstride);
}

__global__ __launch_bounds__(256) void gemm_mma(
    const __nv_bfloat16* __restrict__ A, const __nv_bfloat16* __restrict__ Bmat,
    float* __restrict__ C, int K3, int ldc,
    long long strideB, long long strideC, int causal)
{
    extern __shared__ char smem[];
    const int tid = threadIdx.x;
    const int lane = tid & 31, wid = tid >> 5;
    const int warp_m = wid >> 2, warp_n = wid & 3;       // 2 x 4 warps
    const int bm = blockIdx.y, bn = blockIdx.x, bz = blockIdx.z;
    const uint32_t sbase = smem_u32(smem);

    int Klen = K3;
    if (causal) { int km = (bm + 1) * 384; if (km < Klen) Klen = km; }
    const int KT = Klen >> 5;

    const __nv_bfloat16* Ag = A + (size_t)bm * 128 * K3;
    const __nv_bfloat16* Bg = Bmat + (size_t)bz * strideB + (size_t)bn * 128 * K3;

    float acc[4][4][4];
    #pragma unroll
    for (int i = 0; i < 4; i++)
        #pragma unroll
        for (int j = 0; j < 4; j++)
            #pragma unroll
            for (int q = 0; q < 4; q++) acc[i][j][q] = 0.f;

    // prologue: preload 3 stages
    #pragma unroll
    for (int s = 0; s < STG - 1; s++) {
        if (s < KT) issue_stage(sbase, Ag, Bg, K3, s, tid);
        CP_COMMIT();
    }

    // precomputed fragment lane addressing
    const int a_row = warp_m * 64 + (lane & 15);
    const int a_c   = lane >> 4;                          // 0/1: k0-7 / k8-15
    const int b_row = warp_n * 32 + (lane & 7) + ((lane >> 4) & 1) * 8;
    const int b_c   = (lane >> 3) & 1;

    for (int kt = 0; kt < KT; kt++) {
        CP_WAIT2();
        __syncthreads();
        if (kt + STG - 1 < KT) issue_stage(sbase, Ag, Bg, K3, kt + STG - 1, tid);
        CP_COMMIT();

        const uint32_t sa = sbase + (uint32_t)(kt & 3) * STAGE_BYTES;
        #pragma unroll
        for (int kh = 0; kh < 2; kh++) {                 // two k16 halves of BK
            uint32_t a[4][4];
            #pragma unroll
            for (int mi = 0; mi < 4; mi++)
                ldsm4(a[mi], sa + swz16(a_row + mi * 16, kh * 2 + a_c));
            uint32_t b[2][4];
            #pragma unroll
            for (int ni = 0; ni < 2; ni++)
                ldsm4(b[ni], sa + TILE_BYTES + swz16(b_row + ni * 16, kh * 2 + b_c));
            #pragma unroll
            for (int mi = 0; mi < 4; mi++)
                #pragma unroll
                for (int nf = 0; nf < 4; nf++)
                    mma16816(acc[mi][nf], a[mi],
                             b[nf >> 1][(nf & 1) * 2], b[nf >> 1][(nf & 1) * 2 + 1]);
        }
    }

    // epilogue
    float* Cb = C + (size_t)bz * strideC;
    const int crow0 = bm * 128 + warp_m * 64 + (lane >> 2);
    const int ccol0 = bn * 128 + warp_n * 32 + (lane & 3) * 2;
    #pragma unroll
    for (int mi = 0; mi < 4; mi++)
        #pragma unroll
        for (int nf = 0; nf < 4; nf++) {
            const int r = crow0 + mi * 16, cc = ccol0 + nf * 8;
            *(float2*)&Cb[(size_t)r * ldc + cc] =
                make_float2(acc[mi][nf][0], acc[mi][nf][1]);
            *(float2*)&Cb[(size_t)(r + 8) * ldc + cc] =
                make_float2(acc[mi][nf][2], acc[mi][nf][3]);
        }
}

// ---------------- triplet store: [Ah|Ah|Al] per 32-chunk --------------------
__device__ __forceinline__ void store3A(__nv_bfloat16* __restrict__ dst,
                                        size_t rowbase, int k, float v)
{
    const int o = k >> 5, j = k & 31;
    const __nv_bfloat16 h = __float2bfloat16_rn(v);
    const __nv_bfloat16 l = __float2bfloat16_rn(v - __bfloat162float(h));
    __nv_bfloat16* p = dst + rowbase + (size_t)o * 96 + j;
    p[0] = h; p[32] = h; p[64] = l;
}
// B side: [Bh|Bl|Bh]
__device__ __forceinline__ void store3B(__nv_bfloat16* __restrict__ dst,
                                        size_t rowbase, int k, float v)
{
    const int o = k >> 5, j = k & 31;
    const __nv_bfloat16 h = __float2bfloat16_rn(v);
    const __nv_bfloat16 l = __float2bfloat16_rn(v - __bfloat162float(h));
    __nv_bfloat16* p = dst + rowbase + (size_t)o * 96 + j;
    p[0] = h; p[32] = l; p[64] = h;
}

// ---------------- prep / elementwise kernels --------------------------------

// x [16384,1024] fp32 -> x3 triplet (A operand)
__global__ __launch_bounds__(256) void split_x(const float* __restrict__ src,
    __nv_bfloat16* __restrict__ dst)
{
    const size_t idx = (size_t)blockIdx.x * 256 + threadIdx.x;
    const size_t m = idx >> 8;
    const int k = (int)(idx & 255) * 4;
    const float4 v = ((const float4*)src)[idx];
    const size_t rb = m * 3072;
    store3A(dst, rb, k + 0, v.x);
    store3A(dst, rb, k + 1, v.y);
    store3A(dst, rb, k + 2, v.z);
    store3A(dst, rb, k + 3, v.w);
}

// W [rows=K, cols=N] fp32 -> B operand [N, 3K] triplet (transpose + split)
__global__ __launch_bounds__(256) void tr_split(const float* __restrict__ W,
    __nv_bfloat16* __restrict__ dst, int rows, int cols)
{
    __shared__ float t[32][33];
    const int tx = threadIdx.x & 31, ty = threadIdx.x >> 5;
    const int k0 = blockIdx.x * 32, n0 = blockIdx.y * 32;
    #pragma unroll
    for (int j = 0; j < 4; j++)
        t[ty + 8 * j][tx] = W[(size_t)(k0 + ty + 8 * j) * cols + n0 + tx];
    __syncthreads();
    const int K3 = 3 * rows;
    #pragma unroll
    for (int j = 0; j < 4; j++) {
        const int n = n0 + ty + 8 * j;
        store3B(dst, (size_t)n * K3, k0 + tx, t[tx][ty + 8 * j]);
    }
}

// ke = exp(k - rowmax); kv = ke*v, in place in proj
__global__ __launch_bounds__(256) void kv_transform(float* __restrict__ proj)
{
    const size_t row = blockIdx.x;
    float* kp = proj + row * 3072 + 1024;
    float* vp = proj + row * 3072 + 2048;
    __shared__ float red[256];
    const int tid = threadIdx.x;

    float m = -INFINITY;
    #pragma unroll
    for (int i = 0; i < 4; i++) m = fmaxf(m, kp[tid + 256 * i]);
    red[tid] = m;
    __syncthreads();
    #pragma unroll
    for (int s = 128; s > 0; s >>= 1) {
        if (tid < s) red[tid] = fmaxf(red[tid], red[tid + s]);
        __syncthreads();
    }
    const float mk = red[0];

    #pragma unroll
    for (int i = 0; i < 4; i++) {
        const int idx = tid + 256 * i;
        const float ke = expf(kp[idx] - mk);
        vp[idx] = ke * vp[idx];
        kp[idx] = ke;
    }
}

// [ke|kv] from proj -> kv3 [b][n=chan][t] triplet (B operand, K = t)
__global__ __launch_bounds__(256) void tr_kv(const float* __restrict__ proj,
    __nv_bfloat16* __restrict__ dst)
{
    __shared__ float t[32][33];
    const int tx = threadIdx.x & 31, ty = threadIdx.x >> 5;
    const int b = blockIdx.z >> 1, which = blockIdx.z & 1;
    const int t0 = blockIdx.x * 32, d0 = blockIdx.y * 32;
    const float* src = proj + (size_t)b * 2048 * 3072 + 1024 + which * 1024;
    #pragma unroll
    for (int j = 0; j < 4; j++)
        t[ty + 8 * j][tx] = src[(size_t)(t0 + ty + 8 * j) * 3072 + d0 + tx];
    __syncthreads();
    #pragma unroll
    for (int j = 0; j < 4; j++) {
        const int n = which * 1024 + d0 + ty + 8 * j;
        const size_t rb = ((size_t)b * 2048 + n) * 6144;
        store3B(dst, rb, t0 + tx, t[tx][ty + 8 * j]);
    }
}

// expbias row i -> eb3 triplet (A operand, K = j)
__global__ __launch_bounds__(256) void build_expbias(const float* __restrict__ pb,
    __nv_bfloat16* __restrict__ dst)
{
    const int i = blockIdx.x;
    const float* row = pb + (size_t)i * 2048;
    __shared__ float red[256];
    const int tid = threadIdx.x;

    float m = -INFINITY;
    for (int j = tid; j <= i; j += 256) m = fmaxf(m, row[j]);
    red[tid] = m;
    __syncthreads();
    #pragma unroll
    for (int s = 128; s > 0; s >>= 1) {
        if (tid < s) red[tid] = fmaxf(red[tid], red[tid + s]);
        __syncthreads();
    }
    const float mb = red[0];

    const size_t rb = (size_t)i * 6144;
    for (int j = tid; j < 2048; j += 256) {
        const float v = (j <= i) ? expf(row[j] - mb) : 0.f;
        store3A(dst, rb, j, v);
    }
}

// y = sigmoid(q) * num / denom -> y3 triplet (A operand, written over x3)
__global__ __launch_bounds__(256) void combine(const float* __restrict__ proj,
    const float* __restrict__ nd, __nv_bfloat16* __restrict__ dst)
{
    const size_t idx = (size_t)blockIdx.x * 256 + threadIdx.x;
    const size_t m = idx >> 8;
    const int d4 = (int)(idx & 255) * 4;

    const float4 q   = *(const float4*)(proj + m * 3072 + d4);
    const float4 den = *(const float4*)(nd + m * 2048 + d4);
    const float4 num = *(const float4*)(nd + m * 2048 + 1024 + d4);

    const size_t rb = m * 3072;
    store3A(dst, rb, d4 + 0, (num.x / den.x) / (1.f + expf(-q.x)));
    store3A(dst, rb, d4 + 1, (num.y / den.y) / (1.f + expf(-q.y)));
    store3A(dst, rb, d4 + 2, (num.z / den.z) / (1.f + expf(-q.z)));
    store3A(dst, rb, d4 + 3, (num.w / den.w) / (1.f + expf(-q.w)));
}

// ---------------------------------------------------------------------------
extern "C" void kernel_launch(void* const* d_in, const int* in_sizes, int n_in,
                              void* d_out, int out_size)
{
    const float* x      = (const float*)d_in[0];   // [8,2048,1024]
    const float* w_attn = (const float*)d_in[1];   // [1024,3072]
    const float* w_proj = (const float*)d_in[2];   // [1024,1024]
    const float* pb     = (const float*)d_in[3];   // [2048,2048]
    float* out = (float*)d_out;                    // [8,2048,1024]

    float *proj, *nd;
    __nv_bfloat16 *x3, *wa3, *wp3, *eb3, *kv3;
    cudaGetSymbolAddress((void**)&proj, g_proj);
    cudaGetSymbolAddress((void**)&nd,   g_nd);
    cudaGetSymbolAddress((void**)&x3,   g_x3);
    cudaGetSymbolAddress((void**)&wa3,  g_wa3);
    cudaGetSymbolAddress((void**)&wp3,  g_wp3);
    cudaGetSymbolAddress((void**)&eb3,  g_eb3);
    cudaGetSymbolAddress((void**)&kv3,  g_kv3);
    __nv_bfloat16* y3 = x3;   // alias: x3 dead after K1, y3 born after

    cudaFuncSetAttribute(gemm_mma, cudaFuncAttributeMaxDynamicSharedMemorySize,
                         GEMM_SMEM);

    // operand prep
    split_x<<<16384, 256>>>(x, x3);
    tr_split<<<dim3(32, 96), 256>>>(w_attn, wa3, 1024, 3072);
    tr_split<<<dim3(32, 32), 256>>>(w_proj, wp3, 1024, 1024);

    // K1: proj = x @ w_attn   (M=16384, N=3072, K'=3072)
    gemm_mma<<<dim3(24, 128, 1), 256, GEMM_SMEM>>>(
        x3, wa3, proj, 3072, 3072, 0, 0, 0);

    kv_transform<<<16384, 256>>>(proj);
    build_expbias<<<2048, 256>>>(pb, eb3);
    tr_kv<<<dim3(64, 32, 16), 256>>>(proj, kv3);

    // K3: nd[b] = eb @ [ke|kv]^T  (M=2048, N=2048, K'=6144, causal, 8 batches)
    gemm_mma<<<dim3(16, 16, 8), 256, GEMM_SMEM>>>(
        eb3, kv3, nd, 6144, 2048,
        (long long)2048 * 6144, (long long)2048 * 2048, 1);

    combine<<<16384, 256>>>(proj, nd, y3);

    // K5: out = y @ w_proj    (M=16384, N=1024, K'=3072)
    gemm_mma<<<dim3(8, 128, 1), 256, GEMM_SMEM>>>(
        y3, wp3, out, 3072, 1024, 0, 0, 0);
}